// round 4
// baseline (speedup 1.0000x reference)
#include <cuda_runtime.h>
#include <cstdint>

#define B_    8
#define L_    4096
#define DM_   512
#define H_    8
#define D_    64
#define BH_   64
#define KTOP_ 8
#define M_    (B_ * L_)   // 32768

// ---------------- scratch (device globals; no allocations allowed) ----------
__device__ float  g_q[BH_ * D_ * L_];      // [bh][d][l]  (transposed)
__device__ float  g_k[BH_ * D_ * L_];      // [bh][d][l]
__device__ float  g_v[BH_ * L_ * D_];      // [bh][l][d]
__device__ float2 g_P[BH_ * 8 * L_];       // per-(bh,group-of-8-d) partial sums
__device__ float  g_corr[BH_ * L_];
__device__ float  g_w[BH_ * KTOP_];
__device__ int    g_i[BH_ * KTOP_];
__device__ float  g_ctx[B_ * L_ * DM_];

// ---------------- tf32 helpers ----------------------------------------------
__device__ __forceinline__ unsigned f2tf(float f) {
    unsigned u;
    asm("cvt.rna.tf32.f32 %0, %1;" : "=r"(u) : "f"(f));
    return u;
}

// ---------------- GEMM: C[m,n] = sum_k A[m,k]*W[n,k] + bias[n] ---------------
// 3xTF32: hi/lo split done ONCE at smem-store time; inner loop is LDS+MMA only.
// K = N = 512. MODE 0: row-major [M,512]. MODE 1: scatter to [B,H,L,D].
// MODE 2: scatter transposed to [B,H,D,L].
#define TIDX(buf, r, c) ((buf) * 2560 + (r) * 20 + (c))

template <int MODE>
__global__ void __launch_bounds__(256) gemm512(const float* __restrict__ A,
                                               const float* __restrict__ W,
                                               const float* __restrict__ bias,
                                               float* __restrict__ out) {
    constexpr int K = 512;
    extern __shared__ __align__(16) unsigned smem_u[];
    unsigned* Ah = smem_u;              // [2][128][20]
    unsigned* Al = Ah + 5120;
    unsigned* Wh = Al + 5120;
    unsigned* Wl = Wh + 5120;

    const int tid  = threadIdx.x;
    const int bm   = blockIdx.x * 128;
    const int bn   = blockIdx.y * 128;
    const int warp = tid >> 5, lane = tid & 31;
    const int g  = lane >> 2, tg = lane & 3;
    const int wm = (warp >> 1) * 32;  // 4 warps along M
    const int wn = (warp & 1) * 64;   // 2 warps along N

    float c[2][8][4];
#pragma unroll
    for (int i = 0; i < 2; i++)
#pragma unroll
        for (int j = 0; j < 8; j++)
#pragma unroll
            for (int r = 0; r < 4; r++) c[i][j][r] = 0.f;

    const int r0 = tid >> 2;          // 0..63
    const int c4 = (tid & 3) * 4;     // 0,4,8,12

    auto load_tile = [&](int kt, float4& A0, float4& A1, float4& W0, float4& W1) {
        const int k0 = kt * 16;
        A0 = *(const float4*)&A[(size_t)(bm + r0) * K + k0 + c4];
        A1 = *(const float4*)&A[(size_t)(bm + r0 + 64) * K + k0 + c4];
        W0 = *(const float4*)&W[(size_t)(bn + r0) * K + k0 + c4];
        W1 = *(const float4*)&W[(size_t)(bn + r0 + 64) * K + k0 + c4];
    };
    auto split4 = [&](float4 v, uint4& h, uint4& l) {
        h.x = f2tf(v.x); l.x = f2tf(v.x - __uint_as_float(h.x));
        h.y = f2tf(v.y); l.y = f2tf(v.y - __uint_as_float(h.y));
        h.z = f2tf(v.z); l.z = f2tf(v.z - __uint_as_float(h.z));
        h.w = f2tf(v.w); l.w = f2tf(v.w - __uint_as_float(h.w));
    };
    auto store_tile = [&](int buf, float4 A0, float4 A1, float4 W0, float4 W1) {
        uint4 h, l;
        split4(A0, h, l);
        *(uint4*)&Ah[TIDX(buf, r0, c4)] = h;      *(uint4*)&Al[TIDX(buf, r0, c4)] = l;
        split4(A1, h, l);
        *(uint4*)&Ah[TIDX(buf, r0 + 64, c4)] = h; *(uint4*)&Al[TIDX(buf, r0 + 64, c4)] = l;
        split4(W0, h, l);
        *(uint4*)&Wh[TIDX(buf, r0, c4)] = h;      *(uint4*)&Wl[TIDX(buf, r0, c4)] = l;
        split4(W1, h, l);
        *(uint4*)&Wh[TIDX(buf, r0 + 64, c4)] = h; *(uint4*)&Wl[TIDX(buf, r0 + 64, c4)] = l;
    };

    auto compute = [&](int buf) {
#pragma unroll
        for (int kk = 0; kk < 2; kk++) {
            const int k0 = kk * 8;
            unsigned ah[2][4], al[2][4];
#pragma unroll
            for (int im = 0; im < 2; im++) {
                const int m0 = wm + im * 16;
                ah[im][0] = Ah[TIDX(buf, m0 + g,     k0 + tg)];
                ah[im][1] = Ah[TIDX(buf, m0 + g + 8, k0 + tg)];
                ah[im][2] = Ah[TIDX(buf, m0 + g,     k0 + tg + 4)];
                ah[im][3] = Ah[TIDX(buf, m0 + g + 8, k0 + tg + 4)];
                al[im][0] = Al[TIDX(buf, m0 + g,     k0 + tg)];
                al[im][1] = Al[TIDX(buf, m0 + g + 8, k0 + tg)];
                al[im][2] = Al[TIDX(buf, m0 + g,     k0 + tg + 4)];
                al[im][3] = Al[TIDX(buf, m0 + g + 8, k0 + tg + 4)];
            }
#pragma unroll
            for (int jn = 0; jn < 8; jn++) {
                const int n0 = wn + jn * 8;
                unsigned bh0 = Wh[TIDX(buf, n0 + g, k0 + tg)];
                unsigned bh1 = Wh[TIDX(buf, n0 + g, k0 + tg + 4)];
                unsigned bl0 = Wl[TIDX(buf, n0 + g, k0 + tg)];
                unsigned bl1 = Wl[TIDX(buf, n0 + g, k0 + tg + 4)];
#pragma unroll
                for (int im = 0; im < 2; im++) {
                    asm volatile(
                        "mma.sync.aligned.m16n8k8.row.col.f32.tf32.tf32.f32 "
                        "{%0,%1,%2,%3},{%4,%5,%6,%7},{%8,%9},{%0,%1,%2,%3};"
                        : "+f"(c[im][jn][0]), "+f"(c[im][jn][1]),
                          "+f"(c[im][jn][2]), "+f"(c[im][jn][3])
                        : "r"(ah[im][0]), "r"(ah[im][1]), "r"(ah[im][2]),
                          "r"(ah[im][3]), "r"(bh0), "r"(bh1));
                    asm volatile(
                        "mma.sync.aligned.m16n8k8.row.col.f32.tf32.tf32.f32 "
                        "{%0,%1,%2,%3},{%4,%5,%6,%7},{%8,%9},{%0,%1,%2,%3};"
                        : "+f"(c[im][jn][0]), "+f"(c[im][jn][1]),
                          "+f"(c[im][jn][2]), "+f"(c[im][jn][3])
                        : "r"(ah[im][0]), "r"(ah[im][1]), "r"(ah[im][2]),
                          "r"(ah[im][3]), "r"(bl0), "r"(bl1));
                    asm volatile(
                        "mma.sync.aligned.m16n8k8.row.col.f32.tf32.tf32.f32 "
                        "{%0,%1,%2,%3},{%4,%5,%6,%7},{%8,%9},{%0,%1,%2,%3};"
                        : "+f"(c[im][jn][0]), "+f"(c[im][jn][1]),
                          "+f"(c[im][jn][2]), "+f"(c[im][jn][3])
                        : "r"(al[im][0]), "r"(al[im][1]), "r"(al[im][2]),
                          "r"(al[im][3]), "r"(bh0), "r"(bh1));
                }
            }
        }
    };

    float4 a0, a1, w0, w1;
    load_tile(0, a0, a1, w0, w1);
    store_tile(0, a0, a1, w0, w1);
    __syncthreads();

    for (int kt = 0; kt < 32; kt++) {
        const int buf = kt & 1;
        float4 na0, na1, nw0, nw1;
        if (kt < 31) load_tile(kt + 1, na0, na1, nw0, nw1);
        compute(buf);
        if (kt < 31) store_tile(buf ^ 1, na0, na1, nw0, nw1);
        __syncthreads();
    }

    // epilogue
#pragma unroll
    for (int im = 0; im < 2; im++) {
#pragma unroll
        for (int jn = 0; jn < 8; jn++) {
            const int mrow = bm + wm + im * 16 + g;
            const int ncol = bn + wn + jn * 8 + 2 * tg;
            const float bv0 = bias[ncol], bv1 = bias[ncol + 1];
            float v00 = c[im][jn][0] + bv0;
            float v01 = c[im][jn][1] + bv1;
            float v10 = c[im][jn][2] + bv0;
            float v11 = c[im][jn][3] + bv1;
            if (MODE == 0) {
                out[(size_t)mrow * 512 + ncol]           = v00;
                out[(size_t)mrow * 512 + ncol + 1]       = v01;
                out[(size_t)(mrow + 8) * 512 + ncol]     = v10;
                out[(size_t)(mrow + 8) * 512 + ncol + 1] = v11;
            } else if (MODE == 1) {
                const int h = ncol >> 6, d = ncol & 63;
                const int b = mrow >> 12, l = mrow & 4095;
                size_t base = (((size_t)(b * 8 + h)) * 4096 + l) * 64 + d;
                out[base]     = v00;
                out[base + 1] = v01;
                out[base + 8 * 64]     = v10;     // l+8 in same (b,h)
                out[base + 8 * 64 + 1] = v11;
            } else {
                // MODE 2: [bh][d][l];  (b*8+h)*64+d == b*512 + ncol
                const int b = mrow >> 12, l = mrow & 4095;
                size_t base = ((size_t)(b * 512 + ncol)) * 4096 + l;
                out[base]        = v00;
                out[base + 4096] = v01;           // d+1
                out[base + 8]        = v10;       // l+8
                out[base + 4096 + 8] = v11;
            }
        }
    }
}

// ---------------- 4096-pt radix-4 Stockham FFT in smem -----------------------
// 6 stages (even # of swaps -> result in x). tw[j] = exp(-2*pi*i*j/4096),
// j in [0,4096). 512 threads, each does 2 radix-4 butterflies per stage.
__device__ __forceinline__ float2 cmul(float2 a, float2 b) {
    return make_float2(a.x * b.x - a.y * b.y, a.x * b.y + a.y * b.x);
}

__device__ void fft4096r4(float2* x, float2* y, const float2* tw, int tid) {
    int ls = 0;   // log2(s), s = 4^stage
#pragma unroll 1
    for (int stage = 0; stage < 6; stage++) {
        const int s = 1 << ls;
#pragma unroll
        for (int t = tid; t < 1024; t += 512) {
            const int q  = t & (s - 1);
            const int tq = t - q;           // = p * s
            float2 a0 = x[t];
            float2 a1 = x[t + 1024];
            float2 a2 = x[t + 2048];
            float2 a3 = x[t + 3072];
            float2 t0 = make_float2(a0.x + a2.x, a0.y + a2.y);
            float2 t1 = make_float2(a0.x - a2.x, a0.y - a2.y);
            float2 t2 = make_float2(a1.x + a3.x, a1.y + a3.y);
            float2 t3 = make_float2(a1.x - a3.x, a1.y - a3.y);
            float2 z0 = make_float2(t0.x + t2.x, t0.y + t2.y);
            float2 z2 = make_float2(t0.x - t2.x, t0.y - t2.y);
            float2 z1 = make_float2(t1.x + t3.y, t1.y - t3.x);  // t1 - i*t3
            float2 z3 = make_float2(t1.x - t3.y, t1.y + t3.x);  // t1 + i*t3
            const int ob = 4 * t - 3 * q;   // q + 4*s*p
            y[ob]         = z0;
            y[ob + s]     = cmul(tw[tq], z1);
            y[ob + 2 * s] = cmul(tw[2 * tq], z2);
            y[ob + 3 * s] = cmul(tw[3 * tq], z3);
        }
        __syncthreads();
        float2* tmp = x; x = y; y = tmp;
        ls += 2;
    }
}

// ---------------- Phase A: packed FFT(q+ik), 8 d's per block, reduce ---------
__global__ void __launch_bounds__(512) fwd_corr_kernel() {
    extern __shared__ float2 sm[];
    float2* b0 = sm;            // 4096
    float2* b1 = sm + 4096;     // 4096
    float2* tw = sm + 8192;     // 4096
    const int tid = threadIdx.x;
    for (int j = tid; j < 4096; j += 512) {
        float s, c;
        sincospif(-(float)j / 2048.0f, &s, &c);
        tw[j] = make_float2(c, s);
    }
    const int bh = blockIdx.x >> 3, grp = blockIdx.x & 7;
    const float* qb = g_q + ((size_t)bh * 64 + grp * 8) * 4096;
    const float* kb = g_k + ((size_t)bh * 64 + grp * 8) * 4096;

    float2 acc[8];
#pragma unroll
    for (int j = 0; j < 8; j++) acc[j] = make_float2(0.f, 0.f);

    for (int dd = 0; dd < 8; dd++) {
        const float* qp = qb + (size_t)dd * 4096;
        const float* kp = kb + (size_t)dd * 4096;
        __syncthreads();   // previous iteration's reads of b0 complete
#pragma unroll
        for (int j = 0; j < 8; j++) {
            int t = tid + j * 512;
            b0[t] = make_float2(qp[t], kp[t]);
        }
        __syncthreads();
        fft4096r4(b0, b1, tw, tid);
#pragma unroll
        for (int j = 0; j < 8; j++) {
            int f = tid + j * 512;
            float2 Z  = b0[f];
            float2 Zm = b0[(4096 - f) & 4095];
            float Qr = 0.5f * (Z.x + Zm.x);
            float Qi = 0.5f * (Z.y - Zm.y);
            float Kr = 0.5f * (Z.y + Zm.y);
            float Ki = 0.5f * (Zm.x - Z.x);
            acc[j].x += Qr * Kr + Qi * Ki;   // conj(Q)*K
            acc[j].y += Qr * Ki - Qi * Kr;
        }
    }
    float2* Pout = g_P + (size_t)blockIdx.x * 4096;
#pragma unroll
    for (int j = 0; j < 8; j++) Pout[tid + j * 512] = acc[j];
}

// ---------------- Phase B: sum 8 partials, forward FFT, Re -> corr -----------
__global__ void __launch_bounds__(512) inv_corr_kernel() {
    extern __shared__ float2 sm[];
    float2* b0 = sm;
    float2* b1 = sm + 4096;
    float2* tw = sm + 8192;
    const int tid = threadIdx.x;
    for (int j = tid; j < 4096; j += 512) {
        float s, c;
        sincospif(-(float)j / 2048.0f, &s, &c);
        tw[j] = make_float2(c, s);
    }
    const int bh = blockIdx.x;
    const float2* Pp = g_P + (size_t)bh * 8 * 4096;
    float2 acc[8];
#pragma unroll
    for (int j = 0; j < 8; j++) acc[j] = make_float2(0.f, 0.f);
    for (int grp = 0; grp < 8; grp++) {
#pragma unroll
        for (int j = 0; j < 8; j++) {
            float2 v = Pp[(size_t)grp * 4096 + tid + j * 512];
            acc[j].x += v.x;
            acc[j].y += v.y;
        }
    }
#pragma unroll
    for (int j = 0; j < 8; j++) b0[tid + j * 512] = acc[j];
    __syncthreads();
    fft4096r4(b0, b1, tw, tid);
    const float sc = 1.0f / (4096.0f * 64.0f);   // irfft 1/L and mean 1/D
    for (int t = tid; t < 4096; t += 512)
        g_corr[(size_t)bh * L_ + t] = b0[t].x * sc;
}

// ---------------- Phase C: top-8 + softmax (corr cached in smem) -------------
__global__ void __launch_bounds__(256) topk_kernel() {
    const int bh = blockIdx.x;
    const float* cr = g_corr + (size_t)bh * L_;
    __shared__ float scr[4096];
    __shared__ float svals[256];
    __shared__ int   sidx[256];
    __shared__ int   chosen[KTOP_];
    __shared__ float chval[KTOP_];
    const int tid = threadIdx.x;
    for (int t = tid; t < 4096; t += 256) scr[t] = cr[t];
    __syncthreads();
    for (int it = 0; it < KTOP_; it++) {
        float best = -3.0e38f;
        int bi = -1;
        for (int t = tid; t < 4096; t += 256) {
            float v = scr[t];
            bool used = false;
            for (int u = 0; u < it; u++)
                if (chosen[u] == t) used = true;
            if (!used && (v > best || (v == best && t < bi))) { best = v; bi = t; }
        }
        svals[tid] = best;
        sidx[tid] = bi;
        __syncthreads();
        for (int off = 128; off > 0; off >>= 1) {
            if (tid < off) {
                if (svals[tid + off] > svals[tid] ||
                    (svals[tid + off] == svals[tid] && sidx[tid + off] < sidx[tid])) {
                    svals[tid] = svals[tid + off];
                    sidx[tid]  = sidx[tid + off];
                }
            }
            __syncthreads();
        }
        if (tid == 0) { chosen[it] = sidx[0]; chval[it] = svals[0]; }
        __syncthreads();
    }
    if (tid == 0) {
        float mx = chval[0];  // iteration 0 found the global max
        float e[KTOP_], se = 0.f;
        for (int u = 0; u < KTOP_; u++) { e[u] = expf(chval[u] - mx); se += e[u]; }
        float inv = 1.0f / se;
        for (int u = 0; u < KTOP_; u++) {
            g_w[bh * KTOP_ + u] = e[u] * inv;
            g_i[bh * KTOP_ + u] = chosen[u];
        }
    }
}

// ---------------- Phase D: weighted circular gather of V ---------------------
__global__ void __launch_bounds__(256) gather_kernel() {
    const int bh = blockIdx.y;
    const int b = bh >> 3, h = bh & 7;
    const int li = threadIdx.x >> 6;
    const int d  = threadIdx.x & 63;
    const int l  = blockIdx.x * 4 + li;
    __shared__ float w[KTOP_];
    __shared__ int   ix[KTOP_];
    if (threadIdx.x < KTOP_) {
        w[threadIdx.x]  = g_w[bh * KTOP_ + threadIdx.x];
        ix[threadIdx.x] = g_i[bh * KTOP_ + threadIdx.x];
    }
    __syncthreads();
    const float* vp = g_v + (size_t)bh * L_ * D_;
    float acc = 0.f;
#pragma unroll
    for (int u = 0; u < KTOP_; u++) {
        const int src = (l + ix[u]) & 4095;
        acc += w[u] * vp[(size_t)src * 64 + d];
    }
    g_ctx[((size_t)(b * L_ + l)) * DM_ + h * 64 + d] = acc;
}

// ---------------- launch ------------------------------------------------------
extern "C" void kernel_launch(void* const* d_in, const int* in_sizes, int n_in,
                              void* d_out, int out_size) {
    const float* x  = (const float*)d_in[0];
    const float* Wq = (const float*)d_in[1];
    const float* bq = (const float*)d_in[2];
    const float* Wk = (const float*)d_in[3];
    const float* bk = (const float*)d_in[4];
    const float* Wv = (const float*)d_in[5];
    const float* bv = (const float*)d_in[6];
    const float* Wo = (const float*)d_in[7];
    const float* bo = (const float*)d_in[8];
    float* out = (float*)d_out;

    float *qp, *kp, *vp, *ctxp;
    cudaGetSymbolAddress((void**)&qp, g_q);
    cudaGetSymbolAddress((void**)&kp, g_k);
    cudaGetSymbolAddress((void**)&vp, g_v);
    cudaGetSymbolAddress((void**)&ctxp, g_ctx);

    const int GEMM_SMEM = 81920;   // 4 arrays * 2 bufs * 128*20 * 4B
    const int FFT_SMEM  = 98304;   // (4096+4096+4096) float2
    cudaFuncSetAttribute(gemm512<0>, cudaFuncAttributeMaxDynamicSharedMemorySize, GEMM_SMEM);
    cudaFuncSetAttribute(gemm512<1>, cudaFuncAttributeMaxDynamicSharedMemorySize, GEMM_SMEM);
    cudaFuncSetAttribute(gemm512<2>, cudaFuncAttributeMaxDynamicSharedMemorySize, GEMM_SMEM);
    cudaFuncSetAttribute(fwd_corr_kernel, cudaFuncAttributeMaxDynamicSharedMemorySize, FFT_SMEM);
    cudaFuncSetAttribute(inv_corr_kernel, cudaFuncAttributeMaxDynamicSharedMemorySize, FFT_SMEM);

    dim3 gg(M_ / 128, 4);
    gemm512<2><<<gg, 256, GEMM_SMEM>>>(x, Wq, bq, qp);
    gemm512<2><<<gg, 256, GEMM_SMEM>>>(x, Wk, bk, kp);
    gemm512<1><<<gg, 256, GEMM_SMEM>>>(x, Wv, bv, vp);
    fwd_corr_kernel<<<512, 512, FFT_SMEM>>>();
    inv_corr_kernel<<<64, 512, FFT_SMEM>>>();
    topk_kernel<<<64, 256>>>();
    gather_kernel<<<dim3(1024, 64), 256>>>();
    gemm512<0><<<gg, 256, GEMM_SMEM>>>(ctxp, Wo, bo, out);
}

// round 6
// speedup vs baseline: 1.5559x; 1.5559x over previous
#include <cuda_runtime.h>
#include <cuda_bf16.h>
#include <cstdint>

#define B_    8
#define L_    4096
#define DM_   512
#define H_    8
#define D_    64
#define BH_   64
#define KTOP_ 8
#define M_    (B_ * L_)   // 32768

// ---------------- scratch (device globals; no allocations allowed) ----------
__device__ float  g_q[BH_ * D_ * L_];      // [bh][d][l]  (transposed)
__device__ float  g_k[BH_ * D_ * L_];      // [bh][d][l]
__device__ float  g_v[BH_ * L_ * D_];      // [bh][l][d]
__device__ float2 g_P[BH_ * 8 * L_];       // per-(bh,group-of-8-d) partials
__device__ float  g_corr[BH_ * L_];
__device__ float  g_w[BH_ * KTOP_];
__device__ int    g_i[BH_ * KTOP_];
__device__ float  g_ctx[B_ * L_ * DM_];

// ---------------- bf16 pack/split helpers ------------------------------------
// pack2(x, y) -> bf16x2 word, low half = bf16(x), high half = bf16(y)
__device__ __forceinline__ unsigned pack2(float x, float y) {
    unsigned d;
    asm("cvt.rn.bf16x2.f32 %0, %1, %2;" : "=r"(d) : "f"(y), "f"(x));
    return d;
}
// split 2 floats into (hi bf16x2, lo bf16x2) with lo = rn(v - widen(hi))
__device__ __forceinline__ void split2(float x, float y, unsigned& h, unsigned& l) {
    h = pack2(x, y);
    float hx = __uint_as_float(h << 16);
    float hy = __uint_as_float(h & 0xFFFF0000u);
    l = pack2(x - hx, y - hy);
}

// ---------------- GEMM: C[m,n] = sum_k A[m,k]*W[n,k] + bias[n] ---------------
// 3xBF16: a = ah + al, w = wh + wl (bf16); acc += ah*wh + ah*wl + al*wh, all
// via mma.sync.m16n8k16 bf16 with fp32 accumulate. Split done once at smem
// store; inner loop is pure LDS + HMMA.
// K = N = 512. MODE 0: row-major [M,512]. MODE 1: [B,H,L,D]. MODE 2: [B,H,D,L].
#define TIDX(buf, r, c) ((buf) * 1280 + (r) * 10 + (c))

template <int MODE>
__global__ void __launch_bounds__(256) gemm512(const float* __restrict__ A,
                                               const float* __restrict__ W,
                                               const float* __restrict__ bias,
                                               float* __restrict__ out) {
    constexpr int K = 512;
    // bf16x2 pair words: [2 buf][128 rows][8 pairs + 2 pad]
    __shared__ __align__(16) unsigned Ah[2560], Al[2560], Wh[2560], Wl[2560];

    const int tid  = threadIdx.x;
    const int bm   = blockIdx.x * 128;
    const int bn   = blockIdx.y * 128;
    const int warp = tid >> 5, lane = tid & 31;
    const int g  = lane >> 2, tg = lane & 3;
    const int wm = (warp >> 1) * 32;  // 4 warps along M
    const int wn = (warp & 1) * 64;   // 2 warps along N

    float c[2][8][4];
#pragma unroll
    for (int i = 0; i < 2; i++)
#pragma unroll
        for (int j = 0; j < 8; j++)
#pragma unroll
            for (int r = 0; r < 4; r++) c[i][j][r] = 0.f;

    const int r0 = tid >> 2;          // 0..63
    const int c4 = (tid & 3) * 4;     // float offset 0,4,8,12
    const int p0 = (tid & 3) * 2;     // pair-word offset 0,2,4,6

    auto load_tile = [&](int kt, float4& A0, float4& A1, float4& W0, float4& W1) {
        const int k0 = kt * 16;
        A0 = *(const float4*)&A[(size_t)(bm + r0) * K + k0 + c4];
        A1 = *(const float4*)&A[(size_t)(bm + r0 + 64) * K + k0 + c4];
        W0 = *(const float4*)&W[(size_t)(bn + r0) * K + k0 + c4];
        W1 = *(const float4*)&W[(size_t)(bn + r0 + 64) * K + k0 + c4];
    };
    auto store_one = [&](unsigned* H, unsigned* L, int buf, int row, float4 v) {
        unsigned h01, l01, h23, l23;
        split2(v.x, v.y, h01, l01);
        split2(v.z, v.w, h23, l23);
        *(uint2*)&H[TIDX(buf, row, p0)] = make_uint2(h01, h23);
        *(uint2*)&L[TIDX(buf, row, p0)] = make_uint2(l01, l23);
    };
    auto store_tile = [&](int buf, float4 A0, float4 A1, float4 W0, float4 W1) {
        store_one(Ah, Al, buf, r0,      A0);
        store_one(Ah, Al, buf, r0 + 64, A1);
        store_one(Wh, Wl, buf, r0,      W0);
        store_one(Wh, Wl, buf, r0 + 64, W1);
    };

#define MMA16(C, A0r, A1r, A2r, A3r, B0r, B1r)                                \
    asm volatile(                                                             \
        "mma.sync.aligned.m16n8k16.row.col.f32.bf16.bf16.f32 "                \
        "{%0,%1,%2,%3},{%4,%5,%6,%7},{%8,%9},{%0,%1,%2,%3};"                  \
        : "+f"((C)[0]), "+f"((C)[1]), "+f"((C)[2]), "+f"((C)[3])              \
        : "r"(A0r), "r"(A1r), "r"(A2r), "r"(A3r), "r"(B0r), "r"(B1r))

    auto compute = [&](int buf) {
        unsigned ah[2][4], al[2][4];
#pragma unroll
        for (int im = 0; im < 2; im++) {
            const int m0 = wm + im * 16;
            ah[im][0] = Ah[TIDX(buf, m0 + g,     tg)];
            ah[im][1] = Ah[TIDX(buf, m0 + g + 8, tg)];
            ah[im][2] = Ah[TIDX(buf, m0 + g,     tg + 4)];
            ah[im][3] = Ah[TIDX(buf, m0 + g + 8, tg + 4)];
            al[im][0] = Al[TIDX(buf, m0 + g,     tg)];
            al[im][1] = Al[TIDX(buf, m0 + g + 8, tg)];
            al[im][2] = Al[TIDX(buf, m0 + g,     tg + 4)];
            al[im][3] = Al[TIDX(buf, m0 + g + 8, tg + 4)];
        }
#pragma unroll
        for (int jn = 0; jn < 8; jn++) {
            const int n0 = wn + jn * 8;
            unsigned bh0 = Wh[TIDX(buf, n0 + g, tg)];
            unsigned bh1 = Wh[TIDX(buf, n0 + g, tg + 4)];
            unsigned bl0 = Wl[TIDX(buf, n0 + g, tg)];
            unsigned bl1 = Wl[TIDX(buf, n0 + g, tg + 4)];
#pragma unroll
            for (int im = 0; im < 2; im++) {
                MMA16(c[im][jn], ah[im][0], ah[im][1], ah[im][2], ah[im][3], bh0, bh1);
                MMA16(c[im][jn], ah[im][0], ah[im][1], ah[im][2], ah[im][3], bl0, bl1);
                MMA16(c[im][jn], al[im][0], al[im][1], al[im][2], al[im][3], bh0, bh1);
            }
        }
    };

    float4 a0, a1, w0, w1;
    load_tile(0, a0, a1, w0, w1);
    store_tile(0, a0, a1, w0, w1);
    __syncthreads();

    for (int kt = 0; kt < 32; kt++) {
        const int buf = kt & 1;
        float4 na0, na1, nw0, nw1;
        if (kt < 31) load_tile(kt + 1, na0, na1, nw0, nw1);
        compute(buf);
        if (kt < 31) store_tile(buf ^ 1, na0, na1, nw0, nw1);
        __syncthreads();
    }

    // epilogue
#pragma unroll
    for (int im = 0; im < 2; im++) {
#pragma unroll
        for (int jn = 0; jn < 8; jn++) {
            const int mrow = bm + wm + im * 16 + g;
            const int ncol = bn + wn + jn * 8 + 2 * tg;
            const float bv0 = bias[ncol], bv1 = bias[ncol + 1];
            float v00 = c[im][jn][0] + bv0;
            float v01 = c[im][jn][1] + bv1;
            float v10 = c[im][jn][2] + bv0;
            float v11 = c[im][jn][3] + bv1;
            if (MODE == 0) {
                out[(size_t)mrow * 512 + ncol]           = v00;
                out[(size_t)mrow * 512 + ncol + 1]       = v01;
                out[(size_t)(mrow + 8) * 512 + ncol]     = v10;
                out[(size_t)(mrow + 8) * 512 + ncol + 1] = v11;
            } else if (MODE == 1) {
                const int h = ncol >> 6, d = ncol & 63;
                const int b = mrow >> 12, l = mrow & 4095;
                size_t base = (((size_t)(b * 8 + h)) * 4096 + l) * 64 + d;
                out[base]     = v00;
                out[base + 1] = v01;
                out[base + 8 * 64]     = v10;     // l+8 in same (b,h)
                out[base + 8 * 64 + 1] = v11;
            } else {
                // MODE 2: [bh][d][l];  (b*8+h)*64+d == b*512 + ncol
                const int b = mrow >> 12, l = mrow & 4095;
                size_t base = ((size_t)(b * 512 + ncol)) * 4096 + l;
                out[base]        = v00;
                out[base + 4096] = v01;           // d+1
                out[base + 8]        = v10;       // l+8
                out[base + 4096 + 8] = v11;
            }
        }
    }
}

// ---------------- 4096-pt radix-4 Stockham FFT in smem -----------------------
__device__ __forceinline__ float2 cmul(float2 a, float2 b) {
    return make_float2(a.x * b.x - a.y * b.y, a.x * b.y + a.y * b.x);
}

__device__ void fft4096r4(float2* x, float2* y, const float2* tw, int tid) {
    int ls = 0;
#pragma unroll 1
    for (int stage = 0; stage < 6; stage++) {
        const int s = 1 << ls;
#pragma unroll
        for (int t = tid; t < 1024; t += 512) {
            const int q  = t & (s - 1);
            const int tq = t - q;
            float2 a0 = x[t];
            float2 a1 = x[t + 1024];
            float2 a2 = x[t + 2048];
            float2 a3 = x[t + 3072];
            float2 t0 = make_float2(a0.x + a2.x, a0.y + a2.y);
            float2 t1 = make_float2(a0.x - a2.x, a0.y - a2.y);
            float2 t2 = make_float2(a1.x + a3.x, a1.y + a3.y);
            float2 t3 = make_float2(a1.x - a3.x, a1.y - a3.y);
            float2 z0 = make_float2(t0.x + t2.x, t0.y + t2.y);
            float2 z2 = make_float2(t0.x - t2.x, t0.y - t2.y);
            float2 z1 = make_float2(t1.x + t3.y, t1.y - t3.x);
            float2 z3 = make_float2(t1.x - t3.y, t1.y + t3.x);
            const int ob = 4 * t - 3 * q;
            y[ob]         = z0;
            y[ob + s]     = cmul(tw[tq], z1);
            y[ob + 2 * s] = cmul(tw[2 * tq], z2);
            y[ob + 3 * s] = cmul(tw[3 * tq], z3);
        }
        __syncthreads();
        float2* tmp = x; x = y; y = tmp;
        ls += 2;
    }
}

// ---------------- Phase A: packed FFT(q+ik), 8 d's per block, reduce ---------
__global__ void __launch_bounds__(512) fwd_corr_kernel() {
    extern __shared__ float2 sm[];
    float2* b0 = sm;
    float2* b1 = sm + 4096;
    float2* tw = sm + 8192;
    const int tid = threadIdx.x;
    for (int j = tid; j < 4096; j += 512) {
        float s, c;
        sincospif(-(float)j / 2048.0f, &s, &c);
        tw[j] = make_float2(c, s);
    }
    const int bh = blockIdx.x >> 3, grp = blockIdx.x & 7;
    const float* qb = g_q + ((size_t)bh * 64 + grp * 8) * 4096;
    const float* kb = g_k + ((size_t)bh * 64 + grp * 8) * 4096;

    float2 acc[8];
#pragma unroll
    for (int j = 0; j < 8; j++) acc[j] = make_float2(0.f, 0.f);

    for (int dd = 0; dd < 8; dd++) {
        const float* qp = qb + (size_t)dd * 4096;
        const float* kp = kb + (size_t)dd * 4096;
        __syncthreads();
#pragma unroll
        for (int j = 0; j < 8; j++) {
            int t = tid + j * 512;
            b0[t] = make_float2(qp[t], kp[t]);
        }
        __syncthreads();
        fft4096r4(b0, b1, tw, tid);
#pragma unroll
        for (int j = 0; j < 8; j++) {
            int f = tid + j * 512;
            float2 Z  = b0[f];
            float2 Zm = b0[(4096 - f) & 4095];
            float Qr = 0.5f * (Z.x + Zm.x);
            float Qi = 0.5f * (Z.y - Zm.y);
            float Kr = 0.5f * (Z.y + Zm.y);
            float Ki = 0.5f * (Zm.x - Z.x);
            acc[j].x += Qr * Kr + Qi * Ki;   // conj(Q)*K
            acc[j].y += Qr * Ki - Qi * Kr;
        }
    }
    float2* Pout = g_P + (size_t)blockIdx.x * 4096;
#pragma unroll
    for (int j = 0; j < 8; j++) Pout[tid + j * 512] = acc[j];
}

// ---------------- Phase B: sum 8 partials, forward FFT, Re -> corr -----------
__global__ void __launch_bounds__(512) inv_corr_kernel() {
    extern __shared__ float2 sm[];
    float2* b0 = sm;
    float2* b1 = sm + 4096;
    float2* tw = sm + 8192;
    const int tid = threadIdx.x;
    for (int j = tid; j < 4096; j += 512) {
        float s, c;
        sincospif(-(float)j / 2048.0f, &s, &c);
        tw[j] = make_float2(c, s);
    }
    const int bh = blockIdx.x;
    const float2* Pp = g_P + (size_t)bh * 8 * 4096;
    float2 acc[8];
#pragma unroll
    for (int j = 0; j < 8; j++) acc[j] = make_float2(0.f, 0.f);
    for (int grp = 0; grp < 8; grp++) {
#pragma unroll
        for (int j = 0; j < 8; j++) {
            float2 v = Pp[(size_t)grp * 4096 + tid + j * 512];
            acc[j].x += v.x;
            acc[j].y += v.y;
        }
    }
#pragma unroll
    for (int j = 0; j < 8; j++) b0[tid + j * 512] = acc[j];
    __syncthreads();
    fft4096r4(b0, b1, tw, tid);
    const float sc = 1.0f / (4096.0f * 64.0f);
    for (int t = tid; t < 4096; t += 512)
        g_corr[(size_t)bh * L_ + t] = b0[t].x * sc;
}

// ---------------- Phase C: top-8 + softmax (corr cached in smem) -------------
__global__ void __launch_bounds__(256) topk_kernel() {
    const int bh = blockIdx.x;
    const float* cr = g_corr + (size_t)bh * L_;
    __shared__ float scr[4096];
    __shared__ float svals[256];
    __shared__ int   sidx[256];
    __shared__ int   chosen[KTOP_];
    __shared__ float chval[KTOP_];
    const int tid = threadIdx.x;
    for (int t = tid; t < 4096; t += 256) scr[t] = cr[t];
    __syncthreads();
    for (int it = 0; it < KTOP_; it++) {
        float best = -3.0e38f;
        int bi = -1;
        for (int t = tid; t < 4096; t += 256) {
            float v = scr[t];
            bool used = false;
            for (int u = 0; u < it; u++)
                if (chosen[u] == t) used = true;
            if (!used && (v > best || (v == best && t < bi))) { best = v; bi = t; }
        }
        svals[tid] = best;
        sidx[tid] = bi;
        __syncthreads();
        for (int off = 128; off > 0; off >>= 1) {
            if (tid < off) {
                if (svals[tid + off] > svals[tid] ||
                    (svals[tid + off] == svals[tid] && sidx[tid + off] < sidx[tid])) {
                    svals[tid] = svals[tid + off];
                    sidx[tid]  = sidx[tid + off];
                }
            }
            __syncthreads();
        }
        if (tid == 0) { chosen[it] = sidx[0]; chval[it] = svals[0]; }
        __syncthreads();
    }
    if (tid == 0) {
        float mx = chval[0];
        float e[KTOP_], se = 0.f;
        for (int u = 0; u < KTOP_; u++) { e[u] = expf(chval[u] - mx); se += e[u]; }
        float inv = 1.0f / se;
        for (int u = 0; u < KTOP_; u++) {
            g_w[bh * KTOP_ + u] = e[u] * inv;
            g_i[bh * KTOP_ + u] = chosen[u];
        }
    }
}

// ---------------- Phase D: weighted circular gather of V ---------------------
__global__ void __launch_bounds__(256) gather_kernel() {
    const int bh = blockIdx.y;
    const int b = bh >> 3, h = bh & 7;
    const int li = threadIdx.x >> 6;
    const int d  = threadIdx.x & 63;
    const int l  = blockIdx.x * 4 + li;
    __shared__ float w[KTOP_];
    __shared__ int   ix[KTOP_];
    if (threadIdx.x < KTOP_) {
        w[threadIdx.x]  = g_w[bh * KTOP_ + threadIdx.x];
        ix[threadIdx.x] = g_i[bh * KTOP_ + threadIdx.x];
    }
    __syncthreads();
    const float* vp = g_v + (size_t)bh * L_ * D_;
    float acc = 0.f;
#pragma unroll
    for (int u = 0; u < KTOP_; u++) {
        const int src = (l + ix[u]) & 4095;
        acc += w[u] * vp[(size_t)src * 64 + d];
    }
    g_ctx[((size_t)(b * L_ + l)) * DM_ + h * 64 + d] = acc;
}

// ---------------- launch ------------------------------------------------------
extern "C" void kernel_launch(void* const* d_in, const int* in_sizes, int n_in,
                              void* d_out, int out_size) {
    const float* x  = (const float*)d_in[0];
    const float* Wq = (const float*)d_in[1];
    const float* bq = (const float*)d_in[2];
    const float* Wk = (const float*)d_in[3];
    const float* bk = (const float*)d_in[4];
    const float* Wv = (const float*)d_in[5];
    const float* bv = (const float*)d_in[6];
    const float* Wo = (const float*)d_in[7];
    const float* bo = (const float*)d_in[8];
    float* out = (float*)d_out;

    float *qp, *kp, *vp, *ctxp;
    cudaGetSymbolAddress((void**)&qp, g_q);
    cudaGetSymbolAddress((void**)&kp, g_k);
    cudaGetSymbolAddress((void**)&vp, g_v);
    cudaGetSymbolAddress((void**)&ctxp, g_ctx);

    const int FFT_SMEM = 98304;
    cudaFuncSetAttribute(fwd_corr_kernel, cudaFuncAttributeMaxDynamicSharedMemorySize, FFT_SMEM);
    cudaFuncSetAttribute(inv_corr_kernel, cudaFuncAttributeMaxDynamicSharedMemorySize, FFT_SMEM);

    dim3 gg(M_ / 128, 4);
    gemm512<2><<<gg, 256>>>(x, Wq, bq, qp);
    gemm512<2><<<gg, 256>>>(x, Wk, bk, kp);
    gemm512<1><<<gg, 256>>>(x, Wv, bv, vp);
    fwd_corr_kernel<<<512, 512, FFT_SMEM>>>();
    inv_corr_kernel<<<64, 512, FFT_SMEM>>>();
    topk_kernel<<<64, 256>>>();
    gather_kernel<<<dim3(1024, 64), 256>>>();
    gemm512<0><<<gg, 256>>>(ctxp, Wo, bo, out);
}

// round 7
// speedup vs baseline: 1.8678x; 1.2005x over previous
#include <cuda_runtime.h>
#include <cuda_bf16.h>
#include <cstdint>

#define B_    8
#define L_    4096
#define DM_   512
#define H_    8
#define D_    64
#define BH_   64
#define KTOP_ 8
#define M_    (B_ * L_)   // 32768

// ---------------- scratch (device globals; no allocations allowed) ----------
__device__ float  g_q[BH_ * D_ * L_];      // [bh][d][l]  (transposed)
__device__ float  g_k[BH_ * D_ * L_];      // [bh][d][l]
__device__ float  g_v[BH_ * L_ * D_];      // [bh][l][d]
__device__ float2 g_P[BH_ * 8 * L_];       // per-(bh,group-of-8-d) partials
__device__ float  g_corr[BH_ * L_];
__device__ float  g_w[BH_ * KTOP_];
__device__ int    g_i[BH_ * KTOP_];
__device__ float  g_ctx[B_ * L_ * DM_];

// ---------------- bf16 pack/split helpers ------------------------------------
__device__ __forceinline__ unsigned pack2(float x, float y) {
    unsigned d;
    asm("cvt.rn.bf16x2.f32 %0, %1, %2;" : "=r"(d) : "f"(y), "f"(x));
    return d;   // lo half = bf16(x), hi half = bf16(y)
}
__device__ __forceinline__ void split2(float x, float y, unsigned& h, unsigned& l) {
    h = pack2(x, y);
    float hx = __uint_as_float(h << 16);
    float hy = __uint_as_float(h & 0xFFFF0000u);
    l = pack2(x - hx, y - hy);
}

// Swizzled byte offset inside one 4KB k-tile buffer.
// Tile = 128 rows x 16 bf16 (32B/row), 4 rows per 128B line, chunk = 16B.
// chunk index = ((r&3)*2 + half) ^ (line&1)  -> conflict-free ldmatrix phases.
__device__ __forceinline__ int swad(int r, int hf) {
    const int line = r >> 2;
    const int chunk = (((r & 3) * 2 + hf) ^ (line & 1));
    return line * 128 + chunk * 16;
}

#define LDSM4(R, a)                                                           \
    asm volatile("ldmatrix.sync.aligned.m8n8.x4.shared.b16 {%0,%1,%2,%3}, [%4];" \
                 : "=r"((R)[0]), "=r"((R)[1]), "=r"((R)[2]), "=r"((R)[3])     \
                 : "r"(a))

#define MMA16(C, Ar, B0r, B1r)                                                \
    asm volatile(                                                             \
        "mma.sync.aligned.m16n8k16.row.col.f32.bf16.bf16.f32 "                \
        "{%0,%1,%2,%3},{%4,%5,%6,%7},{%8,%9},{%0,%1,%2,%3};"                  \
        : "+f"((C)[0]), "+f"((C)[1]), "+f"((C)[2]), "+f"((C)[3])              \
        : "r"((Ar)[0]), "r"((Ar)[1]), "r"((Ar)[2]), "r"((Ar)[3]),             \
          "r"(B0r), "r"(B1r))

// ---------------- GEMM: C[m,n] = sum_k A[m,k]*W[n,k] + bias[n] ---------------
// 3xBF16 (ah*wh + ah*wl + al*wh), fp32 accum, ldmatrix fragment loads.
// K = N = 512. MODE 0: row-major [M,512]. MODE 1: [B,H,L,D]. MODE 2: [B,H,D,L].
// smem: Ah @0, Al @8192, Wh @16384, Wl @24576; each [2 buf][4096B swizzled]
template <int MODE>
__global__ void __launch_bounds__(256) gemm512(const float* __restrict__ A,
                                               const float* __restrict__ W,
                                               const float* __restrict__ bias,
                                               float* __restrict__ out) {
    constexpr int K = 512;
    __shared__ __align__(128) unsigned char gsm[32768];
    const uint32_t sb = (uint32_t)__cvta_generic_to_shared(gsm);

    const int tid  = threadIdx.x;
    const int bm   = blockIdx.x * 128;
    const int bn   = blockIdx.y * 128;
    const int warp = tid >> 5, lane = tid & 31;
    const int g  = lane >> 2, tg = lane & 3;
    const int wm = (warp >> 1) * 32;  // 4 warps along M
    const int wn = (warp & 1) * 64;   // 2 warps along N

    float c[2][8][4];
#pragma unroll
    for (int i = 0; i < 2; i++)
#pragma unroll
        for (int j = 0; j < 8; j++)
#pragma unroll
            for (int r = 0; r < 4; r++) c[i][j][r] = 0.f;

    const int r0 = tid >> 2;          // 0..63
    const int c4 = (tid & 3) * 4;     // k-offset 0,4,8,12
    const int h_st = c4 >> 3;
    const int rel0 = swad(r0, h_st) + (c4 & 7) * 2;        // uint2-aligned
    const int rel1 = swad(r0 + 64, h_st) + (c4 & 7) * 2;

    // ldmatrix per-lane addresses (relative to buf 0)
    const int lr = lane & 7, gI = lane >> 3;
    uint32_t aA[2], aW[4];
#pragma unroll
    for (int im = 0; im < 2; im++)
        aA[im] = sb + swad(wm + im * 16 + lr + (gI & 1) * 8, gI >> 1);
#pragma unroll
    for (int jp = 0; jp < 4; jp++)
        aW[jp] = sb + 16384 + swad(wn + jp * 16 + lr + ((gI >> 1) & 1) * 8, gI & 1);

    auto load_tile = [&](int kt, float4& A0, float4& A1, float4& W0, float4& W1) {
        const int k0 = kt * 16;
        A0 = *(const float4*)&A[(size_t)(bm + r0) * K + k0 + c4];
        A1 = *(const float4*)&A[(size_t)(bm + r0 + 64) * K + k0 + c4];
        W0 = *(const float4*)&W[(size_t)(bn + r0) * K + k0 + c4];
        W1 = *(const float4*)&W[(size_t)(bn + r0 + 64) * K + k0 + c4];
    };
    auto store_pair = [&](int baseH, int off, float4 v) {
        unsigned h01, l01, h23, l23;
        split2(v.x, v.y, h01, l01);
        split2(v.z, v.w, h23, l23);
        *(uint2*)(gsm + baseH + off) = make_uint2(h01, h23);
        *(uint2*)(gsm + baseH + 8192 + off) = make_uint2(l01, l23);
    };
    auto store_tile = [&](int buf, float4 A0, float4 A1, float4 W0, float4 W1) {
        const int bo = buf * 4096;
        store_pair(0, bo + rel0, A0);
        store_pair(0, bo + rel1, A1);
        store_pair(16384, bo + rel0, W0);
        store_pair(16384, bo + rel1, W1);
    };

    auto compute = [&](int buf) {
        const uint32_t bo = buf * 4096;
        unsigned ah[2][4], al[2][4];
        LDSM4(ah[0], aA[0] + bo);
        LDSM4(ah[1], aA[1] + bo);
        LDSM4(al[0], aA[0] + 8192 + bo);
        LDSM4(al[1], aA[1] + 8192 + bo);
#pragma unroll
        for (int jp = 0; jp < 4; jp++) {
            unsigned wh[4], wl[4];
            LDSM4(wh, aW[jp] + bo);
            LDSM4(wl, aW[jp] + 8192 + bo);
#pragma unroll
            for (int im = 0; im < 2; im++) {
                MMA16(c[im][2 * jp],     ah[im], wh[0], wh[1]);
                MMA16(c[im][2 * jp],     ah[im], wl[0], wl[1]);
                MMA16(c[im][2 * jp],     al[im], wh[0], wh[1]);
                MMA16(c[im][2 * jp + 1], ah[im], wh[2], wh[3]);
                MMA16(c[im][2 * jp + 1], ah[im], wl[2], wl[3]);
                MMA16(c[im][2 * jp + 1], al[im], wh[2], wh[3]);
            }
        }
    };

    float4 a0, a1, w0, w1;
    load_tile(0, a0, a1, w0, w1);
    store_tile(0, a0, a1, w0, w1);
    __syncthreads();

    for (int kt = 0; kt < 32; kt++) {
        const int buf = kt & 1;
        float4 na0, na1, nw0, nw1;
        if (kt < 31) load_tile(kt + 1, na0, na1, nw0, nw1);
        compute(buf);
        if (kt < 31) store_tile(buf ^ 1, na0, na1, nw0, nw1);
        __syncthreads();
    }

    // epilogue
#pragma unroll
    for (int im = 0; im < 2; im++) {
#pragma unroll
        for (int jn = 0; jn < 8; jn++) {
            const int mrow = bm + wm + im * 16 + g;
            const int ncol = bn + wn + jn * 8 + 2 * tg;
            const float bv0 = bias[ncol], bv1 = bias[ncol + 1];
            float v00 = c[im][jn][0] + bv0;
            float v01 = c[im][jn][1] + bv1;
            float v10 = c[im][jn][2] + bv0;
            float v11 = c[im][jn][3] + bv1;
            if (MODE == 0) {
                out[(size_t)mrow * 512 + ncol]           = v00;
                out[(size_t)mrow * 512 + ncol + 1]       = v01;
                out[(size_t)(mrow + 8) * 512 + ncol]     = v10;
                out[(size_t)(mrow + 8) * 512 + ncol + 1] = v11;
            } else if (MODE == 1) {
                const int h = ncol >> 6, d = ncol & 63;
                const int b = mrow >> 12, l = mrow & 4095;
                size_t base = (((size_t)(b * 8 + h)) * 4096 + l) * 64 + d;
                out[base]     = v00;
                out[base + 1] = v01;
                out[base + 8 * 64]     = v10;     // l+8 in same (b,h)
                out[base + 8 * 64 + 1] = v11;
            } else {
                // MODE 2: [bh][d][l];  (b*8+h)*64+d == b*512 + ncol
                const int b = mrow >> 12, l = mrow & 4095;
                size_t base = ((size_t)(b * 512 + ncol)) * 4096 + l;
                out[base]        = v00;
                out[base + 4096] = v01;           // d+1
                out[base + 8]        = v10;       // l+8
                out[base + 4096 + 8] = v11;
            }
        }
    }
}

// ---------------- 4096-pt radix-8 Stockham FFT in smem -----------------------
__device__ __forceinline__ float2 cmul(float2 a, float2 b) {
    return make_float2(a.x * b.x - a.y * b.y, a.x * b.y + a.y * b.x);
}
__device__ __forceinline__ float2 cadd(float2 a, float2 b) {
    return make_float2(a.x + b.x, a.y + b.y);
}
__device__ __forceinline__ float2 csub(float2 a, float2 b) {
    return make_float2(a.x - b.x, a.y - b.y);
}

// 4 stages (8^4 = 4096), one radix-8 butterfly per thread (512 threads).
// tw[j] = exp(-2*pi*i*j/4096). Even # of buffer swaps -> result in x.
__device__ void fft4096r8(float2* x, float2* y, const float2* tw, int tid) {
    int ls = 0;
#pragma unroll 1
    for (int stage = 0; stage < 4; stage++) {
        const int s = 1 << ls;
        const int q = tid & (s - 1);
        const int sp = tid - q;     // s * p
        float2 a0 = x[tid];
        float2 a1 = x[tid + 512];
        float2 a2 = x[tid + 1024];
        float2 a3 = x[tid + 1536];
        float2 a4 = x[tid + 2048];
        float2 a5 = x[tid + 2560];
        float2 a6 = x[tid + 3072];
        float2 a7 = x[tid + 3584];
        // DFT4 of evens (a0,a2,a4,a6)
        float2 t0 = cadd(a0, a4), t1 = csub(a0, a4);
        float2 t2 = cadd(a2, a6), t3 = csub(a2, a6);
        float2 E0 = cadd(t0, t2), E2 = csub(t0, t2);
        float2 E1 = make_float2(t1.x + t3.y, t1.y - t3.x);   // t1 - i t3
        float2 E3 = make_float2(t1.x - t3.y, t1.y + t3.x);   // t1 + i t3
        // DFT4 of odds (a1,a3,a5,a7)
        float2 u0 = cadd(a1, a5), u1 = csub(a1, a5);
        float2 u2 = cadd(a3, a7), u3 = csub(a3, a7);
        float2 O0 = cadd(u0, u2), O2 = csub(u0, u2);
        float2 O1 = make_float2(u1.x + u3.y, u1.y - u3.x);
        float2 O3 = make_float2(u1.x - u3.y, u1.y + u3.x);
        // multiply odds by W8^j
        const float r = 0.70710678118654752f;
        float2 P1 = make_float2(r * (O1.x + O1.y), r * (O1.y - O1.x)); // *W8
        float2 P2 = make_float2(O2.y, -O2.x);                          // *-i
        float2 P3 = make_float2(r * (O3.y - O3.x), -r * (O3.x + O3.y)); // *W8^3
        const int ob = 8 * tid - 7 * q;   // q + 8*s*p
        y[ob]         = cadd(E0, O0);
        y[ob + s]     = cmul(tw[sp],     cadd(E1, P1));
        y[ob + 2 * s] = cmul(tw[2 * sp], cadd(E2, P2));
        y[ob + 3 * s] = cmul(tw[3 * sp], cadd(E3, P3));
        y[ob + 4 * s] = cmul(tw[4 * sp], csub(E0, O0));
        y[ob + 5 * s] = cmul(tw[5 * sp], csub(E1, P1));
        y[ob + 6 * s] = cmul(tw[6 * sp], csub(E2, P2));
        y[ob + 7 * s] = cmul(tw[7 * sp], csub(E3, P3));
        __syncthreads();
        float2* tmp = x; x = y; y = tmp;
        ls += 3;
    }
}

// ---------------- Phase A: packed FFT(q+ik), 8 d's per block, reduce ---------
__global__ void __launch_bounds__(512) fwd_corr_kernel() {
    extern __shared__ float2 sm[];
    float2* b0 = sm;
    float2* b1 = sm + 4096;
    float2* tw = sm + 8192;
    const int tid = threadIdx.x;
    for (int j = tid; j < 4096; j += 512) {
        float s, c;
        sincospif(-(float)j / 2048.0f, &s, &c);
        tw[j] = make_float2(c, s);
    }
    const int bh = blockIdx.x >> 3, grp = blockIdx.x & 7;
    const float* qb = g_q + ((size_t)bh * 64 + grp * 8) * 4096;
    const float* kb = g_k + ((size_t)bh * 64 + grp * 8) * 4096;

    float2 acc[8];
#pragma unroll
    for (int j = 0; j < 8; j++) acc[j] = make_float2(0.f, 0.f);

    for (int dd = 0; dd < 8; dd++) {
        const float* qp = qb + (size_t)dd * 4096;
        const float* kp = kb + (size_t)dd * 4096;
        __syncthreads();
#pragma unroll
        for (int j = 0; j < 8; j++) {
            int t = tid + j * 512;
            b0[t] = make_float2(qp[t], kp[t]);
        }
        __syncthreads();
        fft4096r8(b0, b1, tw, tid);
#pragma unroll
        for (int j = 0; j < 8; j++) {
            int f = tid + j * 512;
            float2 Z  = b0[f];
            float2 Zm = b0[(4096 - f) & 4095];
            float Qr = 0.5f * (Z.x + Zm.x);
            float Qi = 0.5f * (Z.y - Zm.y);
            float Kr = 0.5f * (Z.y + Zm.y);
            float Ki = 0.5f * (Zm.x - Z.x);
            acc[j].x += Qr * Kr + Qi * Ki;   // conj(Q)*K
            acc[j].y += Qr * Ki - Qi * Kr;
        }
    }
    float2* Pout = g_P + (size_t)blockIdx.x * 4096;
#pragma unroll
    for (int j = 0; j < 8; j++) Pout[tid + j * 512] = acc[j];
}

// ---------------- Phase B: sum 8 partials, forward FFT, Re -> corr -----------
__global__ void __launch_bounds__(512) inv_corr_kernel() {
    extern __shared__ float2 sm[];
    float2* b0 = sm;
    float2* b1 = sm + 4096;
    float2* tw = sm + 8192;
    const int tid = threadIdx.x;
    for (int j = tid; j < 4096; j += 512) {
        float s, c;
        sincospif(-(float)j / 2048.0f, &s, &c);
        tw[j] = make_float2(c, s);
    }
    const int bh = blockIdx.x;
    const float2* Pp = g_P + (size_t)bh * 8 * 4096;
    float2 acc[8];
#pragma unroll
    for (int j = 0; j < 8; j++) acc[j] = make_float2(0.f, 0.f);
    for (int grp = 0; grp < 8; grp++) {
#pragma unroll
        for (int j = 0; j < 8; j++) {
            float2 v = Pp[(size_t)grp * 4096 + tid + j * 512];
            acc[j].x += v.x;
            acc[j].y += v.y;
        }
    }
#pragma unroll
    for (int j = 0; j < 8; j++) b0[tid + j * 512] = acc[j];
    __syncthreads();
    fft4096r8(b0, b1, tw, tid);
    const float sc = 1.0f / (4096.0f * 64.0f);
    for (int t = tid; t < 4096; t += 512)
        g_corr[(size_t)bh * L_ + t] = b0[t].x * sc;
}

// ---------------- Phase C: top-8 + softmax (corr cached in smem) -------------
__global__ void __launch_bounds__(256) topk_kernel() {
    const int bh = blockIdx.x;
    const float* cr = g_corr + (size_t)bh * L_;
    __shared__ float scr[4096];
    __shared__ float svals[256];
    __shared__ int   sidx[256];
    __shared__ int   chosen[KTOP_];
    __shared__ float chval[KTOP_];
    const int tid = threadIdx.x;
    for (int t = tid; t < 4096; t += 256) scr[t] = cr[t];
    __syncthreads();
    for (int it = 0; it < KTOP_; it++) {
        float best = -3.0e38f;
        int bi = -1;
        for (int t = tid; t < 4096; t += 256) {
            float v = scr[t];
            bool used = false;
            for (int u = 0; u < it; u++)
                if (chosen[u] == t) used = true;
            if (!used && (v > best || (v == best && t < bi))) { best = v; bi = t; }
        }
        svals[tid] = best;
        sidx[tid] = bi;
        __syncthreads();
        for (int off = 128; off > 0; off >>= 1) {
            if (tid < off) {
                if (svals[tid + off] > svals[tid] ||
                    (svals[tid + off] == svals[tid] && sidx[tid + off] < sidx[tid])) {
                    svals[tid] = svals[tid + off];
                    sidx[tid]  = sidx[tid + off];
                }
            }
            __syncthreads();
        }
        if (tid == 0) { chosen[it] = sidx[0]; chval[it] = svals[0]; }
        __syncthreads();
    }
    if (tid == 0) {
        float mx = chval[0];
        float e[KTOP_], se = 0.f;
        for (int u = 0; u < KTOP_; u++) { e[u] = expf(chval[u] - mx); se += e[u]; }
        float inv = 1.0f / se;
        for (int u = 0; u < KTOP_; u++) {
            g_w[bh * KTOP_ + u] = e[u] * inv;
            g_i[bh * KTOP_ + u] = chosen[u];
        }
    }
}

// ---------------- Phase D: weighted circular gather of V ---------------------
__global__ void __launch_bounds__(256) gather_kernel() {
    const int bh = blockIdx.y;
    const int b = bh >> 3, h = bh & 7;
    const int li = threadIdx.x >> 6;
    const int d  = threadIdx.x & 63;
    const int l  = blockIdx.x * 4 + li;
    __shared__ float w[KTOP_];
    __shared__ int   ix[KTOP_];
    if (threadIdx.x < KTOP_) {
        w[threadIdx.x]  = g_w[bh * KTOP_ + threadIdx.x];
        ix[threadIdx.x] = g_i[bh * KTOP_ + threadIdx.x];
    }
    __syncthreads();
    const float* vp = g_v + (size_t)bh * L_ * D_;
    float acc = 0.f;
#pragma unroll
    for (int u = 0; u < KTOP_; u++) {
        const int src = (l + ix[u]) & 4095;
        acc += w[u] * vp[(size_t)src * 64 + d];
    }
    g_ctx[((size_t)(b * L_ + l)) * DM_ + h * 64 + d] = acc;
}

// ---------------- launch ------------------------------------------------------
extern "C" void kernel_launch(void* const* d_in, const int* in_sizes, int n_in,
                              void* d_out, int out_size) {
    const float* x  = (const float*)d_in[0];
    const float* Wq = (const float*)d_in[1];
    const float* bq = (const float*)d_in[2];
    const float* Wk = (const float*)d_in[3];
    const float* bk = (const float*)d_in[4];
    const float* Wv = (const float*)d_in[5];
    const float* bv = (const float*)d_in[6];
    const float* Wo = (const float*)d_in[7];
    const float* bo = (const float*)d_in[8];
    float* out = (float*)d_out;

    float *qp, *kp, *vp, *ctxp;
    cudaGetSymbolAddress((void**)&qp, g_q);
    cudaGetSymbolAddress((void**)&kp, g_k);
    cudaGetSymbolAddress((void**)&vp, g_v);
    cudaGetSymbolAddress((void**)&ctxp, g_ctx);

    const int FFT_SMEM = 98304;
    cudaFuncSetAttribute(fwd_corr_kernel, cudaFuncAttributeMaxDynamicSharedMemorySize, FFT_SMEM);
    cudaFuncSetAttribute(inv_corr_kernel, cudaFuncAttributeMaxDynamicSharedMemorySize, FFT_SMEM);

    dim3 gg(M_ / 128, 4);
    gemm512<2><<<gg, 256>>>(x, Wq, bq, qp);
    gemm512<2><<<gg, 256>>>(x, Wk, bk, kp);
    gemm512<1><<<gg, 256>>>(x, Wv, bv, vp);
    fwd_corr_kernel<<<512, 512, FFT_SMEM>>>();
    inv_corr_kernel<<<64, 512, FFT_SMEM>>>();
    topk_kernel<<<64, 256>>>();
    gather_kernel<<<dim3(1024, 64), 256>>>();
    gemm512<0><<<gg, 256>>>(ctxp, Wo, bo, out);
}